// round 12
// baseline (speedup 1.0000x reference)
#include <cuda_runtime.h>
#include <math.h>

#define IMGW 128
#define NA   60
#define NPIX 7680
#define NP   625
#define C1C  32
#define C2C  64
#define W    32

/* ------------------- scratch (static device memory) ---------------------- */
__device__ float g_y1s[(size_t)NP * C1C * NA * W];   /* [p][ci][a][32] */
__device__ float g_y2s[(size_t)NP * C2C * NA * W];   /* [p][co][a][32] */
__device__ float g_y3s[NP * NA * W];                 /* [p][a][32] */
__device__ int   g_anchor[NP * NA];
__device__ int   g_nz[NP];
__device__ float g_w2p[C1C * 9 * C2C];               /* [ci*9+k][co] */
__device__ float g_c1[C1C];
__device__ float g_bg2c[9 * C2C];
__device__ float g_bg3[NPIX];
__device__ float g_xbg[25];
__device__ float g_patches[NP * 25];

typedef unsigned long long u64;
__device__ __forceinline__ u64 dup2(float v) {
    u64 r; asm("mov.b64 %0,{%1,%1};" : "=l"(r) : "f"(v)); return r;
}
__device__ __forceinline__ void fma2(u64 &d, u64 a, u64 b) {
    asm("fma.rn.f32x2 %0,%1,%2,%0;" : "+l"(d) : "l"(a), "l"(b));
}
__device__ __forceinline__ float2 unpk(u64 v) {
    float2 r; asm("mov.b64 {%0,%1},%2;" : "=f"(r.x), "=f"(r.y) : "l"(v)); return r;
}

/* -------------------------------- prep ------------------------------------ */
__global__ void prep_kernel(const float* __restrict__ w2,
                            const float* __restrict__ b1,
                            const float* __restrict__ b2) {
    int b = blockIdx.x, t = threadIdx.x;
    if (b < 72) {
        int i = b * 256 + t;
        int co = i / 288, r = i - co * 288;
        int ci = r / 9, k = r - ci * 9;
        g_w2p[(ci * 9 + k) * 64 + co] = w2[i];
        return;
    }
    __shared__ float c1s[32];
    if (t < 32) { float v = fmaxf(b1[t], 0.f); c1s[t] = v; g_c1[t] = v; }
    __syncthreads();
    for (int it = t; it < 576; it += 256) {
        int co = it & 63, cls = it >> 6;
        int ry = cls / 3, rx = cls - ry * 3;
        float s = b2[co];
        for (int ci = 0; ci < 32; ++ci) {
            float wsum = 0.f;
            for (int dy = 0; dy < 3; ++dy) {
                if (ry == 0 && dy == 0) continue;
                if (ry == 2 && dy == 2) continue;
                for (int dx = 0; dx < 3; ++dx) {
                    if (rx == 0 && dx == 0) continue;
                    if (rx == 2 && dx == 2) continue;
                    wsum += w2[co * 288 + ci * 9 + dy * 3 + dx];
                }
            }
            s += wsum * c1s[ci];
        }
        g_bg2c[cls * 64 + co] = fmaxf(s, 0.f);
    }
}

/* ------------------------------ anchors ----------------------------------- */
__global__ void anchors_kernel(const int* __restrict__ masks) {
    __shared__ int nzf;
    int p = blockIdx.x, t = threadIdx.x;
    if (t == 0) nzf = 0;
    __syncthreads();
    if (t < 60) {
        const int* mp = masks + p * NPIX + t * 128;
        int L = -1, R = -1;
        for (int x = 0; x < 128; x += 4) {
            int4 m = *(const int4*)(mp + x);
            if (m.x) { if (L < 0) L = x;     R = x; }
            if (m.y) { if (L < 0) L = x + 1; R = x + 1; }
            if (m.z) { if (L < 0) L = x + 2; R = x + 2; }
            if (m.w) { if (L < 0) L = x + 3; R = x + 3; }
        }
        int anc;
        if (L < 0) anc = 48;
        else {
            nzf = 1;
            int c = (L + R) >> 1;
            anc = c - 16; if (anc < 0) anc = 0; if (anc > 96) anc = 96;
        }
        g_anchor[p * 60 + t] = anc;
    }
    __syncthreads();
    if (t == 0) g_nz[p] = nzf;
}

/* ----------------- conv1 on strips (smem-staged scalar) -------------------- */
__global__ __launch_bounds__(256) void conv1s_kernel(
    const float* __restrict__ sino, const int* __restrict__ masks,
    const float* __restrict__ w1, const float* __restrict__ b1)
{
    int p = blockIdx.x;
    if (!g_nz[p]) return;
    __shared__ float ms[NPIX];
    __shared__ float w1s[288], b1s[32];
    __shared__ int anch[60];
    int t = threadIdx.x;
    for (int i = t; i < 288; i += 256) w1s[i] = w1[i];
    if (t < 32) b1s[t] = b1[t];
    if (t < 60) anch[t] = g_anchor[p * 60 + t];
    const int* mp = masks + p * NPIX;
    for (int i = t; i < NPIX; i += 256) ms[i] = sino[i] * (float)mp[i];
    __syncthreads();

    for (int e = t; e < NA * W; e += 256) {
        int a = e >> 5, u = e & 31;
        int x = anch[a] + u;
        float tap[9];
#pragma unroll
        for (int dy = 0; dy < 3; ++dy) {
            int aa = a + dy - 1;
#pragma unroll
            for (int dx = 0; dx < 3; ++dx) {
                int xx = x + dx - 1;
                float v = 0.f;
                if (aa >= 0 && aa < 60 && xx >= 0 && xx < 128) v = ms[aa * 128 + xx];
                tap[dy * 3 + dx] = v;
            }
        }
        float* op = g_y1s + (size_t)p * (C1C * NA * W) + e;
        for (int ci = 0; ci < 32; ++ci) {
            float s = b1s[ci];
#pragma unroll
            for (int k = 0; k < 9; ++k) s += w1s[ci * 9 + k] * tap[k];
            op[(size_t)ci * (NA * W)] = fmaxf(s, 0.f);
        }
    }
}

/* -- conv2: co-split x4, 6-row chunks, quarter-ci buffer, dup'd input ------ */
/* s_w 4608 + y1h2 8*386*2=6176 + c1 32 = 10816 floats (~43.3KB) + 60 ints */
#define C2S_SMEM ((4608 + 8 * 386 * 2 + 32) * 4 + 60 * 4)

__global__ __launch_bounds__(192, 5) void conv2s_kernel(const float* __restrict__ b2)
{
    int p = blockIdx.y;
    if (!g_nz[p]) return;
    extern __shared__ float sm[];
    float*  s_w  = sm;                       /* [ci*9+k][16 co-quarter] */
    float2* y1h2 = (float2*)(sm + 4608);     /* [8 ci][8*48 +pad2] dup'd pairs */
    float*  c1s  = sm + 4608 + 8 * 386 * 2;  /* 32 */
    int*    anch = (int*)(c1s + 32);         /* 60 */
    int tid = threadIdx.x;
    int coh = blockIdx.x * 16;

    for (int i = tid; i < 4608; i += 192)
        s_w[i] = g_w2p[(i >> 4) * 64 + coh + (i & 15)];
    if (tid < 60) anch[tid] = g_anchor[p * 60 + tid];
    if (tid >= 64 && tid < 96) c1s[tid - 64] = g_c1[tid - 64];
    __syncthreads();

    int rr   = tid >> 5;          /* 0..5 row within chunk */
    int lane = tid & 31;
    int cog  = (lane >> 3) * 4;   /* 4 co within quarter */
    int u0   = (lane & 7) * 4;    /* 4 x */

    const float* y1p = g_y1s + (size_t)p * (C1C * NA * W);

    float bofs[4];
#pragma unroll
    for (int c = 0; c < 4; ++c) bofs[c] = __ldg(&b2[coh + cog + c]);

    int c0 = blockIdx.z * 6;
    int base = 1 << 30;
#pragma unroll
    for (int r = -1; r <= 6; ++r) {
        int a = c0 + r; a = a < 0 ? 0 : (a > 59 ? 59 : a);
        base = min(base, anch[a]);
    }
    base -= 2;

    int a   = c0 + rr;
    int off = anch[a] - base;

    /* staging thread map: 24 threads per ci (192/8) */
    int ciS = tid / 24, tq = tid - ciS * 24;

    u64 acc[2][4];
#pragma unroll
    for (int c = 0; c < 2; ++c)
#pragma unroll
        for (int x = 0; x < 4; ++x) acc[c][x] = 0ULL;

#pragma unroll
    for (int h = 0; h < 4; ++h) {
        /* stage ci quarter [8h, 8h+8) as duplicated (v,v) pairs */
        {
            int cig = 8 * h + ciS;
            const float* srcci = y1p + (size_t)cig * (NA * W);
            float c1v = c1s[cig];
            float2* dstci = y1h2 + ciS * 386;
#pragma unroll
            for (int r = 0; r < 8; ++r) {
                int ar = c0 - 1 + r;
                bool rowok = (ar >= 0) && (ar < 60);
                int anA = rowok ? anch[ar] : 0;
                const float* rowsrc = srcci + ar * 32;
                float2* rowdst = dstci + r * 48;
#pragma unroll
                for (int x = tq; x < 48; x += 24) {
                    int xx = base + x;
                    int u = xx - anA;
                    float v = 0.f;
                    if (rowok && xx >= 0 && xx < 128)
                        v = (u >= 0 && u < 32) ? rowsrc[u] : c1v;
                    rowdst[x] = make_float2(v, v);
                }
            }
        }
        __syncthreads();

        for (int ci = 0; ci < 8; ++ci) {
            const float2* cb = y1h2 + ci * 386 + rr * 48 + off + u0 - 1;
            int cig9 = (8 * h + ci) * 9;
#pragma unroll
            for (int dy = 0; dy < 3; ++dy) {
                const u64* row = (const u64*)(cb + dy * 48);
                u64 dv[6];
#pragma unroll
                for (int k = 0; k < 6; ++k) dv[k] = row[k];
#pragma unroll
                for (int dx = 0; dx < 3; ++dx) {
                    const u64* wp = (const u64*)(s_w + (cig9 + dy * 3 + dx) * 16 + cog);
                    u64 w0 = wp[0], w1 = wp[1];
#pragma unroll
                    for (int x = 0; x < 4; ++x) {
                        fma2(acc[0][x], w0, dv[dx + x]);
                        fma2(acc[1][x], w1, dv[dx + x]);
                    }
                }
            }
        }
        __syncthreads();
    }

    float* ob = g_y2s + ((size_t)p * C2C + coh + cog) * (NA * W) + a * 32 + u0;
#pragma unroll
    for (int cp = 0; cp < 2; ++cp) {
        float blo = bofs[2 * cp], bhi = bofs[2 * cp + 1];
        float2 v0 = unpk(acc[cp][0]), v1 = unpk(acc[cp][1]);
        float2 v2 = unpk(acc[cp][2]), v3 = unpk(acc[cp][3]);
        *(float4*)(ob + (size_t)(2 * cp) * (NA * W)) =
            make_float4(fmaxf(v0.x + blo, 0.f), fmaxf(v1.x + blo, 0.f),
                        fmaxf(v2.x + blo, 0.f), fmaxf(v3.x + blo, 0.f));
        *(float4*)(ob + (size_t)(2 * cp + 1) * (NA * W)) =
            make_float4(fmaxf(v0.y + bhi, 0.f), fmaxf(v1.y + bhi, 0.f),
                        fmaxf(v2.y + bhi, 0.f), fmaxf(v3.y + bhi, 0.f));
    }
}

/* ------------------------- y3 background field ----------------------------- */
__global__ void bg3_kernel(const float* __restrict__ w3, const float* __restrict__ b3) {
    __shared__ float bg2s[576];
    int a = blockIdx.x, x = threadIdx.x;
    for (int i = x; i < 576; i += 128) bg2s[i] = g_bg2c[i];
    __syncthreads();
    float s = b3[0];
    for (int dy = 0; dy < 3; ++dy) {
        int aa = a + dy - 1; if (aa < 0 || aa >= 60) continue;
        int ry = (aa == 0) ? 0 : ((aa == 59) ? 2 : 1);
        for (int dx = 0; dx < 3; ++dx) {
            int xx = x + dx - 1; if (xx < 0 || xx >= 128) continue;
            int rx = (xx == 0) ? 0 : ((xx == 127) ? 2 : 1);
            const float* cp = bg2s + (ry * 3 + rx) * 64;
            int k = dy * 3 + dx;
            for (int ci = 0; ci < 64; ++ci) s += w3[ci * 9 + k] * cp[ci];
        }
    }
    g_bg3[a * 128 + x] = s;
}

/* ---------------------- x_bg = lin(y3_bg), 25 blocks ----------------------- */
__global__ void xbg_kernel(const float* __restrict__ linw, const float* __restrict__ linb) {
    __shared__ float red[8];
    int k = blockIdx.x, t = threadIdx.x;
    const float* wk = linw + k * NPIX;
    float s = 0.f;
    for (int n = t; n < NPIX; n += 256) s += g_bg3[n] * __ldg(&wk[n]);
    for (int o = 16; o; o >>= 1) s += __shfl_down_sync(0xffffffffu, s, o);
    if (!(t & 31)) red[t >> 5] = s;
    __syncthreads();
    if (t == 0) {
        float tot = 0.f;
#pragma unroll
        for (int w = 0; w < 8; ++w) tot += red[w];
        g_xbg[k] = tot + linb[k];
    }
}

/* ---- conv3: chunk-split, ci-double-buffered, 4 CTAs/SM ------------------- */
#define C3S_SMEM ((32 * 388 + 576 + 576) * 4 + 64 * 4)

__global__ __launch_bounds__(256, 4) void conv3s_kernel(
    const float* __restrict__ w3, const float* __restrict__ b3)
{
    int p = blockIdx.y;
    if (!g_nz[p]) return;
    extern __shared__ float sm[];
    float* y2h = sm;                   /* [32 ci][8*48 +pad4] — half of ci */
    float* w3s = sm + 32 * 388;
    float* bgc = w3s + 576;
    int*  anch = (int*)(bgc + 576);
    int t = threadIdx.x;
    for (int i = t; i < 576; i += 256) { w3s[i] = w3[i]; bgc[i] = g_bg2c[i]; }
    if (t < 60) anch[t] = g_anchor[p * 60 + t];
    float b3v = __ldg(&b3[0]);
    const float* y2p = g_y2s + (size_t)p * C2C * (NA * W);
    __syncthreads();

    int c0 = blockIdx.x * 6;
    int ciS = t >> 3, tq = t & 7;       /* 8 threads per ci (256/32) */

    float s = b3v;
    int r_ = t >> 5, u_ = t & 31;
    int a_ = c0 + r_;
    int anca = (t < 192) ? anch[a_] : 0;

#pragma unroll
    for (int h = 0; h < 2; ++h) {
        {
            int cig = 32 * h + ciS;
            const float* srcci = y2p + (size_t)cig * (NA * W);
            float* dstci = y2h + ciS * 388;
#pragma unroll
            for (int r = 0; r < 8; ++r) {
                int ar = c0 - 1 + r;
                bool rowok = (ar >= 0) && (ar < 60);
                int anA = rowok ? anch[ar] : 0;
                int ry = (ar == 0) ? 0 : ((ar == 59) ? 2 : 1);
                const float* rowsrc = srcci + ar * 32;
                float* rowdst = dstci + r * 48;
#pragma unroll
                for (int xi = tq; xi < 48; xi += 8) {
                    float v = 0.f;
                    if (rowok) {
                        int u = xi - 8;
                        int x = anA + u;
                        if (x >= 0 && x < 128) {
                            if (u >= 0 && u < 32) v = rowsrc[u];
                            else {
                                int rx = (x == 0) ? 0 : ((x == 127) ? 2 : 1);
                                v = bgc[(ry * 3 + rx) * 64 + cig];
                            }
                        }
                    }
                    rowdst[xi] = v;
                }
            }
        }
        __syncthreads();

        if (t < 192) {
#pragma unroll
            for (int dy = 0; dy < 3; ++dy) {
                int ar = a_ - 1 + dy;
                int du = anca - ((ar >= 0 && ar < 60) ? anch[ar] : anca);
                int bi = 8 + du + u_ - 1;
                if (bi < 0) bi = 0; if (bi > 45) bi = 45;
                for (int ci = 0; ci < 32; ++ci) {
                    const float* rp = y2h + ci * 388 + (r_ + dy) * 48 + bi;
                    int wi = (32 * h + ci) * 9 + dy * 3;
                    s += w3s[wi + 0] * rp[0]
                       + w3s[wi + 1] * rp[1]
                       + w3s[wi + 2] * rp[2];
                }
            }
        }
        __syncthreads();
    }
    if (t < 192) g_y3s[p * (NA * W) + a_ * 32 + u_] = s;
}

/* --------------------- gather: patches = x_bg + lin·Δ ---------------------- */
__global__ __launch_bounds__(256) void gather_kernel(const float* __restrict__ linw) {
    __shared__ float diff[NA * W];
    __shared__ int anch[60];
    int p = blockIdx.x, t = threadIdx.x;
    if (!g_nz[p]) { if (t < 25) g_patches[p * 25 + t] = g_xbg[t]; return; }
    if (t < 60) anch[t] = g_anchor[p * 60 + t];
    __syncthreads();
    for (int e = t; e < NA * W; e += 256) {
        int a = e >> 5, u = e & 31;
        diff[e] = g_y3s[p * (NA * W) + e] - g_bg3[a * 128 + anch[a] + u];
    }
    __syncthreads();
    int warp = t >> 5, lane = t & 31;
    for (int k = warp; k < 25; k += 8) {
        const float* wk = linw + k * NPIX;
        float s = 0.f;
        for (int e = lane; e < NA * W; e += 32) {
            int a = e >> 5, u = e & 31;
            s += diff[e] * __ldg(&wk[a * 128 + anch[a] + u]);
        }
        for (int o = 16; o; o >>= 1) s += __shfl_down_sync(0xffffffffu, s, o);
        if (!lane) g_patches[p * 25 + k] = g_xbg[k] + s;
    }
}

/* ------------- recon: fused fill + scatter + sigmoid ----------------------- */
__global__ void recon_kernel(float* __restrict__ out) {
    int i = blockIdx.x * 256 + threadIdx.x;
    if (i >= IMGW * IMGW) return;
    int y = i >> 7, x = i & 127;
    float v = 0.5f;
    if (y < 125 && x < 125) {
        int py = y / 5, px = x / 5;
        int qy = y - py * 5, qx = x - px * 5;
        float z = g_patches[(py * 25 + px) * 25 + qy * 5 + qx];
        v = 1.f / (1.f + expf(-z));
    }
    out[i] = v;
}

/* ------------ radon: 512 threads, 4-way s-split + smem reduce -------------- */
__global__ __launch_bounds__(512) void radon_kernel(float* __restrict__ out) {
    __shared__ float part[4][128];
    int a = blockIdx.x;
    int tid = threadIdx.x & 127, sg = threadIdx.x >> 7;
    double ang = (double)a * (M_PI / 180.0);
    float ct = (float)cos(ang), st = (float)sin(ang);
    float t = (float)tid - 63.5f;
    const float* img = out;
    float accum = 0.f;
    for (int ss = sg * 32; ss < sg * 32 + 32; ++ss) {
        float s = (float)ss - 63.5f;
        float x = 63.5f + t * ct - s * st;
        float y = 63.5f + t * st + s * ct;
        float fx = floorf(x), fy = floorf(y);
        int x0 = (int)fx, y0 = (int)fy;
        float wx = x - fx, wy = y - fy;
        float v00 = 0.f, v10 = 0.f, v01 = 0.f, v11 = 0.f;
        if (x0 >= 0 && x0 < 128 && y0 >= 0 && y0 < 128)         v00 = __ldg(&img[y0 * 128 + x0]);
        if (x0 + 1 >= 0 && x0 + 1 < 128 && y0 >= 0 && y0 < 128) v10 = __ldg(&img[y0 * 128 + x0 + 1]);
        if (x0 >= 0 && x0 < 128 && y0 + 1 >= 0 && y0 + 1 < 128) v01 = __ldg(&img[(y0 + 1) * 128 + x0]);
        if (x0 + 1 >= 0 && x0 + 1 < 128 && y0 + 1 >= 0 && y0 + 1 < 128)
            v11 = __ldg(&img[(y0 + 1) * 128 + x0 + 1]);
        accum += v00 * (1.f - wx) * (1.f - wy) + v10 * wx * (1.f - wy)
               + v01 * (1.f - wx) * wy + v11 * wx * wy;
    }
    part[sg][tid] = accum;
    __syncthreads();
    if (threadIdx.x < 128)
        out[IMGW * IMGW + a * 128 + threadIdx.x] =
            part[0][threadIdx.x] + part[1][threadIdx.x] +
            part[2][threadIdx.x] + part[3][threadIdx.x];
}

/* ------------------------------- launch ------------------------------------ */
extern "C" void kernel_launch(void* const* d_in, const int* in_sizes, int n_in,
                              void* d_out, int out_size)
{
    const float* sino   = (const float*)d_in[0];
    const float* w1     = (const float*)d_in[1];
    const float* b1     = (const float*)d_in[2];
    const float* w2     = (const float*)d_in[3];
    const float* b2     = (const float*)d_in[4];
    const float* w3     = (const float*)d_in[5];
    const float* b3     = (const float*)d_in[6];
    const float* linw   = (const float*)d_in[7];
    const float* linb   = (const float*)d_in[8];
    const int*   masks  = (const int*)d_in[9];
    float* out = (float*)d_out;

    cudaFuncSetAttribute(conv2s_kernel, cudaFuncAttributeMaxDynamicSharedMemorySize, C2S_SMEM);
    cudaFuncSetAttribute(conv3s_kernel, cudaFuncAttributeMaxDynamicSharedMemorySize, C3S_SMEM);

    prep_kernel<<<73, 256>>>(w2, b1, b2);                       /* 0 */
    anchors_kernel<<<NP, 64>>>(masks);                          /* 1 */
    conv1s_kernel<<<NP, 256>>>(sino, masks, w1, b1);            /* 2 */
    conv2s_kernel<<<dim3(4, NP, 10), 192, C2S_SMEM>>>(b2);      /* 3 <- profiled */
    bg3_kernel<<<60, 128>>>(w3, b3);                            /* 4 */
    xbg_kernel<<<25, 256>>>(linw, linb);                        /* 5 */
    conv3s_kernel<<<dim3(10, NP), 256, C3S_SMEM>>>(w3, b3);     /* 6 */
    gather_kernel<<<NP, 256>>>(linw);                           /* 7 */
    recon_kernel<<<(IMGW * IMGW + 255) / 256, 256>>>(out);      /* 8 */
    radon_kernel<<<NA, 512>>>(out);                             /* 9 */
}

// round 13
// speedup vs baseline: 1.3180x; 1.3180x over previous
#include <cuda_runtime.h>
#include <math.h>

#define IMGW 128
#define NA   60
#define NPIX 7680
#define NP   625
#define C1C  32
#define C2C  64
#define W    32

/* ------------------- scratch (static device memory) ---------------------- */
__device__ float g_y1s[(size_t)NP * C1C * NA * W];   /* [p][ci][a][32] */
__device__ float g_y2s[(size_t)NP * C2C * NA * W];   /* [p][co][a][32] */
__device__ float g_y3s[NP * NA * W];                 /* [p][a][32] */
__device__ int   g_anchor[NP * NA];
__device__ int   g_nz[NP];
__device__ float g_w2p[C1C * 9 * C2C];               /* [ci*9+k][co] */
__device__ float g_c1[C1C];
__device__ float g_bg2c[9 * C2C];
__device__ float g_bg3[NPIX];
__device__ float g_xbg[25];
__device__ float g_patches[NP * 25];

typedef unsigned long long u64;
__device__ __forceinline__ u64 dup2(float v) {
    u64 r; asm("mov.b64 %0,{%1,%1};" : "=l"(r) : "f"(v)); return r;
}
__device__ __forceinline__ void fma2(u64 &d, u64 a, u64 b) {
    asm("fma.rn.f32x2 %0,%1,%2,%0;" : "+l"(d) : "l"(a), "l"(b));
}
__device__ __forceinline__ float2 unpk(u64 v) {
    float2 r; asm("mov.b64 {%0,%1},%2;" : "=f"(r.x), "=f"(r.y) : "l"(v)); return r;
}

/* -------------------------------- prep ------------------------------------ */
__global__ void prep_kernel(const float* __restrict__ w2,
                            const float* __restrict__ b1,
                            const float* __restrict__ b2) {
    int b = blockIdx.x, t = threadIdx.x;
    if (b < 72) {
        int i = b * 256 + t;
        int co = i / 288, r = i - co * 288;
        int ci = r / 9, k = r - ci * 9;
        g_w2p[(ci * 9 + k) * 64 + co] = w2[i];
        return;
    }
    __shared__ float c1s[32];
    if (t < 32) { float v = fmaxf(b1[t], 0.f); c1s[t] = v; g_c1[t] = v; }
    __syncthreads();
    for (int it = t; it < 576; it += 256) {
        int co = it & 63, cls = it >> 6;
        int ry = cls / 3, rx = cls - ry * 3;
        float s = b2[co];
        for (int ci = 0; ci < 32; ++ci) {
            float wsum = 0.f;
            for (int dy = 0; dy < 3; ++dy) {
                if (ry == 0 && dy == 0) continue;
                if (ry == 2 && dy == 2) continue;
                for (int dx = 0; dx < 3; ++dx) {
                    if (rx == 0 && dx == 0) continue;
                    if (rx == 2 && dx == 2) continue;
                    wsum += w2[co * 288 + ci * 9 + dy * 3 + dx];
                }
            }
            s += wsum * c1s[ci];
        }
        g_bg2c[cls * 64 + co] = fmaxf(s, 0.f);
    }
}

/* ------------------------------ anchors ----------------------------------- */
__global__ void anchors_kernel(const int* __restrict__ masks) {
    __shared__ int nzf;
    int p = blockIdx.x, t = threadIdx.x;
    if (t == 0) nzf = 0;
    __syncthreads();
    if (t < 60) {
        const int* mp = masks + p * NPIX + t * 128;
        int L = -1, R = -1;
        for (int x = 0; x < 128; x += 4) {
            int4 m = *(const int4*)(mp + x);
            if (m.x) { if (L < 0) L = x;     R = x; }
            if (m.y) { if (L < 0) L = x + 1; R = x + 1; }
            if (m.z) { if (L < 0) L = x + 2; R = x + 2; }
            if (m.w) { if (L < 0) L = x + 3; R = x + 3; }
        }
        int anc;
        if (L < 0) anc = 48;
        else {
            nzf = 1;
            int c = (L + R) >> 1;
            anc = c - 16; if (anc < 0) anc = 0; if (anc > 96) anc = 96;
        }
        g_anchor[p * 60 + t] = anc;
    }
    __syncthreads();
    if (t == 0) g_nz[p] = nzf;
}

/* ----------------- conv1 on strips (smem-staged scalar) -------------------- */
__global__ __launch_bounds__(256) void conv1s_kernel(
    const float* __restrict__ sino, const int* __restrict__ masks,
    const float* __restrict__ w1, const float* __restrict__ b1)
{
    int p = blockIdx.x;
    if (!g_nz[p]) return;
    __shared__ float ms[NPIX];
    __shared__ float w1s[288], b1s[32];
    __shared__ int anch[60];
    int t = threadIdx.x;
    for (int i = t; i < 288; i += 256) w1s[i] = w1[i];
    if (t < 32) b1s[t] = b1[t];
    if (t < 60) anch[t] = g_anchor[p * 60 + t];
    const int* mp = masks + p * NPIX;
    for (int i = t; i < NPIX; i += 256) ms[i] = sino[i] * (float)mp[i];
    __syncthreads();

    for (int e = t; e < NA * W; e += 256) {
        int a = e >> 5, u = e & 31;
        int x = anch[a] + u;
        float tap[9];
#pragma unroll
        for (int dy = 0; dy < 3; ++dy) {
            int aa = a + dy - 1;
#pragma unroll
            for (int dx = 0; dx < 3; ++dx) {
                int xx = x + dx - 1;
                float v = 0.f;
                if (aa >= 0 && aa < 60 && xx >= 0 && xx < 128) v = ms[aa * 128 + xx];
                tap[dy * 3 + dx] = v;
            }
        }
        float* op = g_y1s + (size_t)p * (C1C * NA * W) + e;
        for (int ci = 0; ci < 32; ++ci) {
            float s = b1s[ci];
#pragma unroll
            for (int k = 0; k < 9; ++k) s += w1s[ci * 9 + k] * tap[k];
            op[(size_t)ci * (NA * W)] = fmaxf(s, 0.f);
        }
    }
}

/* -- conv2: co-half split, X=8/thread, quarter-ci staging, 4 CTAs/SM ------- */
/* s_w 9216 + y1h 8*388=3104 + c1 32 = 12352 floats (~49.4KB) + 60 ints */
#define C2S_SMEM ((9216 + 8 * 388 + 32) * 4 + 60 * 4)

__global__ __launch_bounds__(192, 4) void conv2s_kernel(const float* __restrict__ b2)
{
    int p = blockIdx.y;
    if (!g_nz[p]) return;
    extern __shared__ float sm[];
    float* s_w  = sm;                 /* [ci*9+k][32 co-half] */
    float* y1h  = sm + 9216;          /* [8 ci][8*48 +pad4]   */
    float* c1s  = y1h + 8 * 388;      /* 32 */
    int*   anch = (int*)(c1s + 32);   /* 60 */
    int tid = threadIdx.x;
    int coh = blockIdx.x * 32;

    for (int i = tid; i < 9216; i += 192)
        s_w[i] = g_w2p[(i >> 5) * 64 + coh + (i & 31)];
    if (tid < 60) anch[tid] = g_anchor[p * 60 + tid];
    if (tid >= 64 && tid < 96) c1s[tid - 64] = g_c1[tid - 64];
    __syncthreads();

    int rr   = tid >> 5;          /* 0..5 row within chunk */
    int lane = tid & 31;
    int cog  = (lane >> 2) * 4;   /* 8 co-groups x 4 co = 32 co (half) */
    int u0   = (lane & 3) * 8;    /* 4 x-lanes x 8 = 32 x */

    const float* y1p = g_y1s + (size_t)p * (C1C * NA * W);

    int c0 = blockIdx.z * 6;
    int base = 1 << 30;
#pragma unroll
    for (int r = -1; r <= 6; ++r) {
        int a = c0 + r; a = a < 0 ? 0 : (a > 59 ? 59 : a);
        base = min(base, anch[a]);
    }
    base -= 2;

    int a   = c0 + rr;
    int off = anch[a] - base;

    /* staging thread map: 24 threads per ci (192/8) */
    int ciS = tid / 24, tq = tid - ciS * 24;

    u64 acc[2][8];
#pragma unroll
    for (int c = 0; c < 2; ++c)
#pragma unroll
        for (int x = 0; x < 8; ++x) acc[c][x] = 0ULL;

#pragma unroll
    for (int h = 0; h < 4; ++h) {
        /* stage ci quarter [8h, 8h+8) — same predicates as R11 */
        {
            int cig = 8 * h + ciS;
            const float* srcci = y1p + (size_t)cig * (NA * W);
            float c1v = c1s[cig];
            float* dstci = y1h + ciS * 388;
#pragma unroll
            for (int r = 0; r < 8; ++r) {
                int ar = c0 - 1 + r;
                bool rowok = (ar >= 0) && (ar < 60);
                int anA = rowok ? anch[ar] : 0;
                const float* rowsrc = srcci + ar * 32;
                float* rowdst = dstci + r * 48;
#pragma unroll
                for (int x = tq; x < 48; x += 24) {
                    int xx = base + x;
                    int u = xx - anA;
                    float v = 0.f;
                    if (rowok && xx >= 0 && xx < 128)
                        v = (u >= 0 && u < 32) ? rowsrc[u] : c1v;
                    rowdst[x] = v;
                }
            }
        }
        __syncthreads();

        for (int ci = 0; ci < 8; ++ci) {
            const float* cb = y1h + ci * 388 + rr * 48 + off + u0 - 1;
            int cig9 = (8 * h + ci) * 9;
#pragma unroll
            for (int dy = 0; dy < 3; ++dy) {
                const float* row = cb + dy * 48;
                u64 dv[10];
#pragma unroll
                for (int k = 0; k < 10; ++k) dv[k] = dup2(row[k]);
#pragma unroll
                for (int dx = 0; dx < 3; ++dx) {
                    const u64* wp = (const u64*)(s_w + (cig9 + dy * 3 + dx) * 32 + cog);
                    u64 w0 = wp[0], w1 = wp[1];
#pragma unroll
                    for (int x = 0; x < 8; ++x) {
                        fma2(acc[0][x], w0, dv[dx + x]);
                        fma2(acc[1][x], w1, dv[dx + x]);
                    }
                }
            }
        }
        __syncthreads();
    }

    float bofs[4];
#pragma unroll
    for (int c = 0; c < 4; ++c) bofs[c] = __ldg(&b2[coh + cog + c]);

    float* ob = g_y2s + ((size_t)p * C2C + coh + cog) * (NA * W) + a * 32 + u0;
#pragma unroll
    for (int cp = 0; cp < 2; ++cp) {
        float blo = bofs[2 * cp], bhi = bofs[2 * cp + 1];
        float lo[8], hi[8];
#pragma unroll
        for (int x = 0; x < 8; ++x) {
            float2 v = unpk(acc[cp][x]);
            lo[x] = fmaxf(v.x + blo, 0.f);
            hi[x] = fmaxf(v.y + bhi, 0.f);
        }
        float* plo = ob + (size_t)(2 * cp) * (NA * W);
        float* phi = ob + (size_t)(2 * cp + 1) * (NA * W);
        *(float4*)(plo)     = make_float4(lo[0], lo[1], lo[2], lo[3]);
        *(float4*)(plo + 4) = make_float4(lo[4], lo[5], lo[6], lo[7]);
        *(float4*)(phi)     = make_float4(hi[0], hi[1], hi[2], hi[3]);
        *(float4*)(phi + 4) = make_float4(hi[4], hi[5], hi[6], hi[7]);
    }
}

/* ------------------------- y3 background field ----------------------------- */
__global__ void bg3_kernel(const float* __restrict__ w3, const float* __restrict__ b3) {
    __shared__ float bg2s[576];
    int a = blockIdx.x, x = threadIdx.x;
    for (int i = x; i < 576; i += 128) bg2s[i] = g_bg2c[i];
    __syncthreads();
    float s = b3[0];
    for (int dy = 0; dy < 3; ++dy) {
        int aa = a + dy - 1; if (aa < 0 || aa >= 60) continue;
        int ry = (aa == 0) ? 0 : ((aa == 59) ? 2 : 1);
        for (int dx = 0; dx < 3; ++dx) {
            int xx = x + dx - 1; if (xx < 0 || xx >= 128) continue;
            int rx = (xx == 0) ? 0 : ((xx == 127) ? 2 : 1);
            const float* cp = bg2s + (ry * 3 + rx) * 64;
            int k = dy * 3 + dx;
            for (int ci = 0; ci < 64; ++ci) s += w3[ci * 9 + k] * cp[ci];
        }
    }
    g_bg3[a * 128 + x] = s;
}

/* ---------------------- x_bg = lin(y3_bg), 25 blocks ----------------------- */
__global__ void xbg_kernel(const float* __restrict__ linw, const float* __restrict__ linb) {
    __shared__ float red[8];
    int k = blockIdx.x, t = threadIdx.x;
    const float* wk = linw + k * NPIX;
    float s = 0.f;
    for (int n = t; n < NPIX; n += 256) s += g_bg3[n] * __ldg(&wk[n]);
    for (int o = 16; o; o >>= 1) s += __shfl_down_sync(0xffffffffu, s, o);
    if (!(t & 31)) red[t >> 5] = s;
    __syncthreads();
    if (t == 0) {
        float tot = 0.f;
#pragma unroll
        for (int w = 0; w < 8; ++w) tot += red[w];
        g_xbg[k] = tot + linb[k];
    }
}

/* ---- conv3: chunk-split, ci-double-buffered, 4 CTAs/SM ------------------- */
#define C3S_SMEM ((32 * 388 + 576 + 576) * 4 + 64 * 4)

__global__ __launch_bounds__(256, 4) void conv3s_kernel(
    const float* __restrict__ w3, const float* __restrict__ b3)
{
    int p = blockIdx.y;
    if (!g_nz[p]) return;
    extern __shared__ float sm[];
    float* y2h = sm;                   /* [32 ci][8*48 +pad4] — half of ci */
    float* w3s = sm + 32 * 388;
    float* bgc = w3s + 576;
    int*  anch = (int*)(bgc + 576);
    int t = threadIdx.x;
    for (int i = t; i < 576; i += 256) { w3s[i] = w3[i]; bgc[i] = g_bg2c[i]; }
    if (t < 60) anch[t] = g_anchor[p * 60 + t];
    float b3v = __ldg(&b3[0]);
    const float* y2p = g_y2s + (size_t)p * C2C * (NA * W);
    __syncthreads();

    int c0 = blockIdx.x * 6;
    int ciS = t >> 3, tq = t & 7;       /* 8 threads per ci (256/32) */

    float s = b3v;
    int r_ = t >> 5, u_ = t & 31;
    int a_ = c0 + r_;
    int anca = (t < 192) ? anch[a_] : 0;

#pragma unroll
    for (int h = 0; h < 2; ++h) {
        {
            int cig = 32 * h + ciS;
            const float* srcci = y2p + (size_t)cig * (NA * W);
            float* dstci = y2h + ciS * 388;
#pragma unroll
            for (int r = 0; r < 8; ++r) {
                int ar = c0 - 1 + r;
                bool rowok = (ar >= 0) && (ar < 60);
                int anA = rowok ? anch[ar] : 0;
                int ry = (ar == 0) ? 0 : ((ar == 59) ? 2 : 1);
                const float* rowsrc = srcci + ar * 32;
                float* rowdst = dstci + r * 48;
#pragma unroll
                for (int xi = tq; xi < 48; xi += 8) {
                    float v = 0.f;
                    if (rowok) {
                        int u = xi - 8;
                        int x = anA + u;
                        if (x >= 0 && x < 128) {
                            if (u >= 0 && u < 32) v = rowsrc[u];
                            else {
                                int rx = (x == 0) ? 0 : ((x == 127) ? 2 : 1);
                                v = bgc[(ry * 3 + rx) * 64 + cig];
                            }
                        }
                    }
                    rowdst[xi] = v;
                }
            }
        }
        __syncthreads();

        if (t < 192) {
#pragma unroll
            for (int dy = 0; dy < 3; ++dy) {
                int ar = a_ - 1 + dy;
                int du = anca - ((ar >= 0 && ar < 60) ? anch[ar] : anca);
                int bi = 8 + du + u_ - 1;
                if (bi < 0) bi = 0; if (bi > 45) bi = 45;
                for (int ci = 0; ci < 32; ++ci) {
                    const float* rp = y2h + ci * 388 + (r_ + dy) * 48 + bi;
                    int wi = (32 * h + ci) * 9 + dy * 3;
                    s += w3s[wi + 0] * rp[0]
                       + w3s[wi + 1] * rp[1]
                       + w3s[wi + 2] * rp[2];
                }
            }
        }
        __syncthreads();
    }
    if (t < 192) g_y3s[p * (NA * W) + a_ * 32 + u_] = s;
}

/* --------------------- gather: patches = x_bg + lin·Δ ---------------------- */
__global__ __launch_bounds__(256) void gather_kernel(const float* __restrict__ linw) {
    __shared__ float diff[NA * W];
    __shared__ int anch[60];
    int p = blockIdx.x, t = threadIdx.x;
    if (!g_nz[p]) { if (t < 25) g_patches[p * 25 + t] = g_xbg[t]; return; }
    if (t < 60) anch[t] = g_anchor[p * 60 + t];
    __syncthreads();
    for (int e = t; e < NA * W; e += 256) {
        int a = e >> 5, u = e & 31;
        diff[e] = g_y3s[p * (NA * W) + e] - g_bg3[a * 128 + anch[a] + u];
    }
    __syncthreads();
    int warp = t >> 5, lane = t & 31;
    for (int k = warp; k < 25; k += 8) {
        const float* wk = linw + k * NPIX;
        float s = 0.f;
        for (int e = lane; e < NA * W; e += 32) {
            int a = e >> 5, u = e & 31;
            s += diff[e] * __ldg(&wk[a * 128 + anch[a] + u]);
        }
        for (int o = 16; o; o >>= 1) s += __shfl_down_sync(0xffffffffu, s, o);
        if (!lane) g_patches[p * 25 + k] = g_xbg[k] + s;
    }
}

/* ------------- recon: fused fill + scatter + sigmoid ----------------------- */
__global__ void recon_kernel(float* __restrict__ out) {
    int i = blockIdx.x * 256 + threadIdx.x;
    if (i >= IMGW * IMGW) return;
    int y = i >> 7, x = i & 127;
    float v = 0.5f;
    if (y < 125 && x < 125) {
        int py = y / 5, px = x / 5;
        int qy = y - py * 5, qx = x - px * 5;
        float z = g_patches[(py * 25 + px) * 25 + qy * 5 + qx];
        v = 1.f / (1.f + expf(-z));
    }
    out[i] = v;
}

/* ------------ radon: 512 threads, 4-way s-split + smem reduce -------------- */
__global__ __launch_bounds__(512) void radon_kernel(float* __restrict__ out) {
    __shared__ float part[4][128];
    int a = blockIdx.x;
    int tid = threadIdx.x & 127, sg = threadIdx.x >> 7;
    double ang = (double)a * (M_PI / 180.0);
    float ct = (float)cos(ang), st = (float)sin(ang);
    float t = (float)tid - 63.5f;
    const float* img = out;
    float accum = 0.f;
    for (int ss = sg * 32; ss < sg * 32 + 32; ++ss) {
        float s = (float)ss - 63.5f;
        float x = 63.5f + t * ct - s * st;
        float y = 63.5f + t * st + s * ct;
        float fx = floorf(x), fy = floorf(y);
        int x0 = (int)fx, y0 = (int)fy;
        float wx = x - fx, wy = y - fy;
        float v00 = 0.f, v10 = 0.f, v01 = 0.f, v11 = 0.f;
        if (x0 >= 0 && x0 < 128 && y0 >= 0 && y0 < 128)         v00 = __ldg(&img[y0 * 128 + x0]);
        if (x0 + 1 >= 0 && x0 + 1 < 128 && y0 >= 0 && y0 < 128) v10 = __ldg(&img[y0 * 128 + x0 + 1]);
        if (x0 >= 0 && x0 < 128 && y0 + 1 >= 0 && y0 + 1 < 128) v01 = __ldg(&img[(y0 + 1) * 128 + x0]);
        if (x0 + 1 >= 0 && x0 + 1 < 128 && y0 + 1 >= 0 && y0 + 1 < 128)
            v11 = __ldg(&img[(y0 + 1) * 128 + x0 + 1]);
        accum += v00 * (1.f - wx) * (1.f - wy) + v10 * wx * (1.f - wy)
               + v01 * (1.f - wx) * wy + v11 * wx * wy;
    }
    part[sg][tid] = accum;
    __syncthreads();
    if (threadIdx.x < 128)
        out[IMGW * IMGW + a * 128 + threadIdx.x] =
            part[0][threadIdx.x] + part[1][threadIdx.x] +
            part[2][threadIdx.x] + part[3][threadIdx.x];
}

/* ------------------------------- launch ------------------------------------ */
extern "C" void kernel_launch(void* const* d_in, const int* in_sizes, int n_in,
                              void* d_out, int out_size)
{
    const float* sino   = (const float*)d_in[0];
    const float* w1     = (const float*)d_in[1];
    const float* b1     = (const float*)d_in[2];
    const float* w2     = (const float*)d_in[3];
    const float* b2     = (const float*)d_in[4];
    const float* w3     = (const float*)d_in[5];
    const float* b3     = (const float*)d_in[6];
    const float* linw   = (const float*)d_in[7];
    const float* linb   = (const float*)d_in[8];
    const int*   masks  = (const int*)d_in[9];
    float* out = (float*)d_out;

    cudaFuncSetAttribute(conv2s_kernel, cudaFuncAttributeMaxDynamicSharedMemorySize, C2S_SMEM);
    cudaFuncSetAttribute(conv3s_kernel, cudaFuncAttributeMaxDynamicSharedMemorySize, C3S_SMEM);

    prep_kernel<<<73, 256>>>(w2, b1, b2);                       /* 0 */
    anchors_kernel<<<NP, 64>>>(masks);                          /* 1 */
    conv1s_kernel<<<NP, 256>>>(sino, masks, w1, b1);            /* 2 */
    conv2s_kernel<<<dim3(2, NP, 10), 192, C2S_SMEM>>>(b2);      /* 3 <- profiled */
    bg3_kernel<<<60, 128>>>(w3, b3);                            /* 4 */
    xbg_kernel<<<25, 256>>>(linw, linb);                        /* 5 */
    conv3s_kernel<<<dim3(10, NP), 256, C3S_SMEM>>>(w3, b3);     /* 6 */
    gather_kernel<<<NP, 256>>>(linw);                           /* 7 */
    recon_kernel<<<(IMGW * IMGW + 255) / 256, 256>>>(out);      /* 8 */
    radon_kernel<<<NA, 512>>>(out);                             /* 9 */
}

// round 14
// speedup vs baseline: 1.3864x; 1.0519x over previous
#include <cuda_runtime.h>
#include <math.h>

#define IMGW 128
#define NA   60
#define NPIX 7680
#define NP   625
#define C1C  32
#define C2C  64
#define W    32

/* ------------------- scratch (static device memory) ---------------------- */
__device__ float g_y1s[(size_t)NP * C1C * NA * W];   /* [p][ci][a][32] */
__device__ float g_y2s[(size_t)NP * C2C * NA * W];   /* [p][co][a][32] */
__device__ float g_y3s[NP * NA * W];                 /* [p][a][32] */
__device__ int   g_anchor[NP * NA];
__device__ int   g_nz[NP];
__device__ float g_w2p[C1C * 9 * C2C];               /* [ci*9+k][co] */
__device__ float g_c1[C1C];
__device__ float g_bg2c[9 * C2C];
__device__ float g_bg3[NPIX];
__device__ float g_xbg[25];
__device__ float g_patches[NP * 25];

typedef unsigned long long u64;
__device__ __forceinline__ u64 dup2(float v) {
    u64 r; asm("mov.b64 %0,{%1,%1};" : "=l"(r) : "f"(v)); return r;
}
__device__ __forceinline__ void fma2(u64 &d, u64 a, u64 b) {
    asm("fma.rn.f32x2 %0,%1,%2,%0;" : "+l"(d) : "l"(a), "l"(b));
}
__device__ __forceinline__ float2 unpk(u64 v) {
    float2 r; asm("mov.b64 {%0,%1},%2;" : "=f"(r.x), "=f"(r.y) : "l"(v)); return r;
}

/* -------------------------------- prep ------------------------------------ */
__global__ void prep_kernel(const float* __restrict__ w2,
                            const float* __restrict__ b1,
                            const float* __restrict__ b2) {
    int b = blockIdx.x, t = threadIdx.x;
    if (b < 72) {
        int i = b * 256 + t;
        int co = i / 288, r = i - co * 288;
        int ci = r / 9, k = r - ci * 9;
        g_w2p[(ci * 9 + k) * 64 + co] = w2[i];
        return;
    }
    __shared__ float c1s[32];
    if (t < 32) { float v = fmaxf(b1[t], 0.f); c1s[t] = v; g_c1[t] = v; }
    __syncthreads();
    for (int it = t; it < 576; it += 256) {
        int co = it & 63, cls = it >> 6;
        int ry = cls / 3, rx = cls - ry * 3;
        float s = b2[co];
        for (int ci = 0; ci < 32; ++ci) {
            float wsum = 0.f;
            for (int dy = 0; dy < 3; ++dy) {
                if (ry == 0 && dy == 0) continue;
                if (ry == 2 && dy == 2) continue;
                for (int dx = 0; dx < 3; ++dx) {
                    if (rx == 0 && dx == 0) continue;
                    if (rx == 2 && dx == 2) continue;
                    wsum += w2[co * 288 + ci * 9 + dy * 3 + dx];
                }
            }
            s += wsum * c1s[ci];
        }
        g_bg2c[cls * 64 + co] = fmaxf(s, 0.f);
    }
}

/* ------------------------------ anchors ----------------------------------- */
__global__ void anchors_kernel(const int* __restrict__ masks) {
    __shared__ int nzf;
    int p = blockIdx.x, t = threadIdx.x;
    if (t == 0) nzf = 0;
    __syncthreads();
    if (t < 60) {
        const int* mp = masks + p * NPIX + t * 128;
        int L = -1, R = -1;
        for (int x = 0; x < 128; x += 4) {
            int4 m = *(const int4*)(mp + x);
            if (m.x) { if (L < 0) L = x;     R = x; }
            if (m.y) { if (L < 0) L = x + 1; R = x + 1; }
            if (m.z) { if (L < 0) L = x + 2; R = x + 2; }
            if (m.w) { if (L < 0) L = x + 3; R = x + 3; }
        }
        int anc;
        if (L < 0) anc = 48;
        else {
            nzf = 1;
            int c = (L + R) >> 1;
            anc = c - 16; if (anc < 0) anc = 0; if (anc > 96) anc = 96;
        }
        g_anchor[p * 60 + t] = anc;
    }
    __syncthreads();
    if (t == 0) g_nz[p] = nzf;
}

/* ----------------- conv1 on strips (smem-staged scalar) -------------------- */
__global__ __launch_bounds__(256) void conv1s_kernel(
    const float* __restrict__ sino, const int* __restrict__ masks,
    const float* __restrict__ w1, const float* __restrict__ b1)
{
    int p = blockIdx.x;
    if (!g_nz[p]) return;
    __shared__ float ms[NPIX];
    __shared__ float w1s[288], b1s[32];
    __shared__ int anch[60];
    int t = threadIdx.x;
    for (int i = t; i < 288; i += 256) w1s[i] = w1[i];
    if (t < 32) b1s[t] = b1[t];
    if (t < 60) anch[t] = g_anchor[p * 60 + t];
    const int* mp = masks + p * NPIX;
    for (int i = t; i < NPIX; i += 256) ms[i] = sino[i] * (float)mp[i];
    __syncthreads();

    for (int e = t; e < NA * W; e += 256) {
        int a = e >> 5, u = e & 31;
        int x = anch[a] + u;
        float tap[9];
#pragma unroll
        for (int dy = 0; dy < 3; ++dy) {
            int aa = a + dy - 1;
#pragma unroll
            for (int dx = 0; dx < 3; ++dx) {
                int xx = x + dx - 1;
                float v = 0.f;
                if (aa >= 0 && aa < 60 && xx >= 0 && xx < 128) v = ms[aa * 128 + xx];
                tap[dy * 3 + dx] = v;
            }
        }
        float* op = g_y1s + (size_t)p * (C1C * NA * W) + e;
        for (int ci = 0; ci < 32; ++ci) {
            float s = b1s[ci];
#pragma unroll
            for (int k = 0; k < 9; ++k) s += w1s[ci * 9 + k] * tap[k];
            op[(size_t)ci * (NA * W)] = fmaxf(s, 0.f);
        }
    }
}

/* -- conv2: co-quarter split, R11 loop, quarter-ci staging, 6 CTAs/SM ------ */
/* s_w 4608 + y1h 8*388=3104 + c1 32 = 7744 floats (~31KB) + 60 ints */
#define C2S_SMEM ((4608 + 8 * 388 + 32) * 4 + 60 * 4)

__global__ __launch_bounds__(192, 6) void conv2s_kernel(const float* __restrict__ b2)
{
    int p = blockIdx.y;
    if (!g_nz[p]) return;
    extern __shared__ float sm[];
    float* s_w  = sm;                 /* [ci*9+k][16 co-quarter] */
    float* y1h  = sm + 4608;          /* [8 ci][8*48 +pad4]      */
    float* c1s  = y1h + 8 * 388;      /* 32 */
    int*   anch = (int*)(c1s + 32);   /* 60 */
    int tid = threadIdx.x;
    int coh = blockIdx.x * 16;

    for (int i = tid; i < 4608; i += 192)
        s_w[i] = g_w2p[(i >> 4) * 64 + coh + (i & 15)];
    if (tid < 60) anch[tid] = g_anchor[p * 60 + tid];
    if (tid >= 64 && tid < 96) c1s[tid - 64] = g_c1[tid - 64];
    __syncthreads();

    int rr   = tid >> 5;          /* 0..5 row within chunk */
    int lane = tid & 31;
    int cog  = (lane >> 3) * 4;   /* 4 co within quarter */
    int u0   = (lane & 7) * 4;    /* 4 x */

    const float* y1p = g_y1s + (size_t)p * (C1C * NA * W);

    float bofs[4];
#pragma unroll
    for (int c = 0; c < 4; ++c) bofs[c] = __ldg(&b2[coh + cog + c]);

    int c0 = blockIdx.z * 6;
    int base = 1 << 30;
#pragma unroll
    for (int r = -1; r <= 6; ++r) {
        int a = c0 + r; a = a < 0 ? 0 : (a > 59 ? 59 : a);
        base = min(base, anch[a]);
    }
    base -= 2;

    int a   = c0 + rr;
    int off = anch[a] - base;

    /* staging thread map: 24 threads per ci (192/8) */
    int ciS = tid / 24, tq = tid - ciS * 24;

    u64 acc[2][4];
#pragma unroll
    for (int c = 0; c < 2; ++c)
#pragma unroll
        for (int x = 0; x < 4; ++x) acc[c][x] = 0ULL;

#pragma unroll
    for (int h = 0; h < 4; ++h) {
        /* stage ci quarter [8h, 8h+8) — identical predicates */
        {
            int cig = 8 * h + ciS;
            const float* srcci = y1p + (size_t)cig * (NA * W);
            float c1v = c1s[cig];
            float* dstci = y1h + ciS * 388;
#pragma unroll
            for (int r = 0; r < 8; ++r) {
                int ar = c0 - 1 + r;
                bool rowok = (ar >= 0) && (ar < 60);
                int anA = rowok ? anch[ar] : 0;
                const float* rowsrc = srcci + ar * 32;
                float* rowdst = dstci + r * 48;
#pragma unroll
                for (int x = tq; x < 48; x += 24) {
                    int xx = base + x;
                    int u = xx - anA;
                    float v = 0.f;
                    if (rowok && xx >= 0 && xx < 128)
                        v = (u >= 0 && u < 32) ? rowsrc[u] : c1v;
                    rowdst[x] = v;
                }
            }
        }
        __syncthreads();

        for (int ci = 0; ci < 8; ++ci) {
            const float* cb = y1h + ci * 388 + rr * 48 + off + u0 - 1;
            int cig9 = (8 * h + ci) * 9;
#pragma unroll
            for (int dy = 0; dy < 3; ++dy) {
                const float* row = cb + dy * 48;
                u64 dv[6];
#pragma unroll
                for (int k = 0; k < 6; ++k) dv[k] = dup2(row[k]);
#pragma unroll
                for (int dx = 0; dx < 3; ++dx) {
                    const u64* wp = (const u64*)(s_w + (cig9 + dy * 3 + dx) * 16 + cog);
                    u64 w0 = wp[0], w1 = wp[1];
#pragma unroll
                    for (int x = 0; x < 4; ++x) {
                        fma2(acc[0][x], w0, dv[dx + x]);
                        fma2(acc[1][x], w1, dv[dx + x]);
                    }
                }
            }
        }
        __syncthreads();
    }

    float* ob = g_y2s + ((size_t)p * C2C + coh + cog) * (NA * W) + a * 32 + u0;
#pragma unroll
    for (int cp = 0; cp < 2; ++cp) {
        float blo = bofs[2 * cp], bhi = bofs[2 * cp + 1];
        float2 v0 = unpk(acc[cp][0]), v1 = unpk(acc[cp][1]);
        float2 v2 = unpk(acc[cp][2]), v3 = unpk(acc[cp][3]);
        *(float4*)(ob + (size_t)(2 * cp) * (NA * W)) =
            make_float4(fmaxf(v0.x + blo, 0.f), fmaxf(v1.x + blo, 0.f),
                        fmaxf(v2.x + blo, 0.f), fmaxf(v3.x + blo, 0.f));
        *(float4*)(ob + (size_t)(2 * cp + 1) * (NA * W)) =
            make_float4(fmaxf(v0.y + bhi, 0.f), fmaxf(v1.y + bhi, 0.f),
                        fmaxf(v2.y + bhi, 0.f), fmaxf(v3.y + bhi, 0.f));
    }
}

/* ------------------------- y3 background field ----------------------------- */
__global__ void bg3_kernel(const float* __restrict__ w3, const float* __restrict__ b3) {
    __shared__ float bg2s[576];
    int a = blockIdx.x, x = threadIdx.x;
    for (int i = x; i < 576; i += 128) bg2s[i] = g_bg2c[i];
    __syncthreads();
    float s = b3[0];
    for (int dy = 0; dy < 3; ++dy) {
        int aa = a + dy - 1; if (aa < 0 || aa >= 60) continue;
        int ry = (aa == 0) ? 0 : ((aa == 59) ? 2 : 1);
        for (int dx = 0; dx < 3; ++dx) {
            int xx = x + dx - 1; if (xx < 0 || xx >= 128) continue;
            int rx = (xx == 0) ? 0 : ((xx == 127) ? 2 : 1);
            const float* cp = bg2s + (ry * 3 + rx) * 64;
            int k = dy * 3 + dx;
            for (int ci = 0; ci < 64; ++ci) s += w3[ci * 9 + k] * cp[ci];
        }
    }
    g_bg3[a * 128 + x] = s;
}

/* ---------------------- x_bg = lin(y3_bg), 25 blocks ----------------------- */
__global__ void xbg_kernel(const float* __restrict__ linw, const float* __restrict__ linb) {
    __shared__ float red[8];
    int k = blockIdx.x, t = threadIdx.x;
    const float* wk = linw + k * NPIX;
    float s = 0.f;
    for (int n = t; n < NPIX; n += 256) s += g_bg3[n] * __ldg(&wk[n]);
    for (int o = 16; o; o >>= 1) s += __shfl_down_sync(0xffffffffu, s, o);
    if (!(t & 31)) red[t >> 5] = s;
    __syncthreads();
    if (t == 0) {
        float tot = 0.f;
#pragma unroll
        for (int w = 0; w < 8; ++w) tot += red[w];
        g_xbg[k] = tot + linb[k];
    }
}

/* ---- conv3: chunk-split, ci-double-buffered, 4 CTAs/SM ------------------- */
#define C3S_SMEM ((32 * 388 + 576 + 576) * 4 + 64 * 4)

__global__ __launch_bounds__(256, 4) void conv3s_kernel(
    const float* __restrict__ w3, const float* __restrict__ b3)
{
    int p = blockIdx.y;
    if (!g_nz[p]) return;
    extern __shared__ float sm[];
    float* y2h = sm;                   /* [32 ci][8*48 +pad4] — half of ci */
    float* w3s = sm + 32 * 388;
    float* bgc = w3s + 576;
    int*  anch = (int*)(bgc + 576);
    int t = threadIdx.x;
    for (int i = t; i < 576; i += 256) { w3s[i] = w3[i]; bgc[i] = g_bg2c[i]; }
    if (t < 60) anch[t] = g_anchor[p * 60 + t];
    float b3v = __ldg(&b3[0]);
    const float* y2p = g_y2s + (size_t)p * C2C * (NA * W);
    __syncthreads();

    int c0 = blockIdx.x * 6;
    int ciS = t >> 3, tq = t & 7;       /* 8 threads per ci (256/32) */

    float s = b3v;
    int r_ = t >> 5, u_ = t & 31;
    int a_ = c0 + r_;
    int anca = (t < 192) ? anch[a_] : 0;

#pragma unroll
    for (int h = 0; h < 2; ++h) {
        {
            int cig = 32 * h + ciS;
            const float* srcci = y2p + (size_t)cig * (NA * W);
            float* dstci = y2h + ciS * 388;
#pragma unroll
            for (int r = 0; r < 8; ++r) {
                int ar = c0 - 1 + r;
                bool rowok = (ar >= 0) && (ar < 60);
                int anA = rowok ? anch[ar] : 0;
                int ry = (ar == 0) ? 0 : ((ar == 59) ? 2 : 1);
                const float* rowsrc = srcci + ar * 32;
                float* rowdst = dstci + r * 48;
#pragma unroll
                for (int xi = tq; xi < 48; xi += 8) {
                    float v = 0.f;
                    if (rowok) {
                        int u = xi - 8;
                        int x = anA + u;
                        if (x >= 0 && x < 128) {
                            if (u >= 0 && u < 32) v = rowsrc[u];
                            else {
                                int rx = (x == 0) ? 0 : ((x == 127) ? 2 : 1);
                                v = bgc[(ry * 3 + rx) * 64 + cig];
                            }
                        }
                    }
                    rowdst[xi] = v;
                }
            }
        }
        __syncthreads();

        if (t < 192) {
#pragma unroll
            for (int dy = 0; dy < 3; ++dy) {
                int ar = a_ - 1 + dy;
                int du = anca - ((ar >= 0 && ar < 60) ? anch[ar] : anca);
                int bi = 8 + du + u_ - 1;
                if (bi < 0) bi = 0; if (bi > 45) bi = 45;
                for (int ci = 0; ci < 32; ++ci) {
                    const float* rp = y2h + ci * 388 + (r_ + dy) * 48 + bi;
                    int wi = (32 * h + ci) * 9 + dy * 3;
                    s += w3s[wi + 0] * rp[0]
                       + w3s[wi + 1] * rp[1]
                       + w3s[wi + 2] * rp[2];
                }
            }
        }
        __syncthreads();
    }
    if (t < 192) g_y3s[p * (NA * W) + a_ * 32 + u_] = s;
}

/* --------------------- gather: patches = x_bg + lin·Δ ---------------------- */
__global__ __launch_bounds__(256) void gather_kernel(const float* __restrict__ linw) {
    __shared__ float diff[NA * W];
    __shared__ int anch[60];
    int p = blockIdx.x, t = threadIdx.x;
    if (!g_nz[p]) { if (t < 25) g_patches[p * 25 + t] = g_xbg[t]; return; }
    if (t < 60) anch[t] = g_anchor[p * 60 + t];
    __syncthreads();
    for (int e = t; e < NA * W; e += 256) {
        int a = e >> 5, u = e & 31;
        diff[e] = g_y3s[p * (NA * W) + e] - g_bg3[a * 128 + anch[a] + u];
    }
    __syncthreads();
    int warp = t >> 5, lane = t & 31;
    for (int k = warp; k < 25; k += 8) {
        const float* wk = linw + k * NPIX;
        float s = 0.f;
        for (int e = lane; e < NA * W; e += 32) {
            int a = e >> 5, u = e & 31;
            s += diff[e] * __ldg(&wk[a * 128 + anch[a] + u]);
        }
        for (int o = 16; o; o >>= 1) s += __shfl_down_sync(0xffffffffu, s, o);
        if (!lane) g_patches[p * 25 + k] = g_xbg[k] + s;
    }
}

/* ------------- recon: fused fill + scatter + sigmoid ----------------------- */
__global__ void recon_kernel(float* __restrict__ out) {
    int i = blockIdx.x * 256 + threadIdx.x;
    if (i >= IMGW * IMGW) return;
    int y = i >> 7, x = i & 127;
    float v = 0.5f;
    if (y < 125 && x < 125) {
        int py = y / 5, px = x / 5;
        int qy = y - py * 5, qx = x - px * 5;
        float z = g_patches[(py * 25 + px) * 25 + qy * 5 + qx];
        v = 1.f / (1.f + expf(-z));
    }
    out[i] = v;
}

/* ------------ radon: 512 threads, 4-way s-split + smem reduce -------------- */
__global__ __launch_bounds__(512) void radon_kernel(float* __restrict__ out) {
    __shared__ float part[4][128];
    int a = blockIdx.x;
    int tid = threadIdx.x & 127, sg = threadIdx.x >> 7;
    double ang = (double)a * (M_PI / 180.0);
    float ct = (float)cos(ang), st = (float)sin(ang);
    float t = (float)tid - 63.5f;
    const float* img = out;
    float accum = 0.f;
    for (int ss = sg * 32; ss < sg * 32 + 32; ++ss) {
        float s = (float)ss - 63.5f;
        float x = 63.5f + t * ct - s * st;
        float y = 63.5f + t * st + s * ct;
        float fx = floorf(x), fy = floorf(y);
        int x0 = (int)fx, y0 = (int)fy;
        float wx = x - fx, wy = y - fy;
        float v00 = 0.f, v10 = 0.f, v01 = 0.f, v11 = 0.f;
        if (x0 >= 0 && x0 < 128 && y0 >= 0 && y0 < 128)         v00 = __ldg(&img[y0 * 128 + x0]);
        if (x0 + 1 >= 0 && x0 + 1 < 128 && y0 >= 0 && y0 < 128) v10 = __ldg(&img[y0 * 128 + x0 + 1]);
        if (x0 >= 0 && x0 < 128 && y0 + 1 >= 0 && y0 + 1 < 128) v01 = __ldg(&img[(y0 + 1) * 128 + x0]);
        if (x0 + 1 >= 0 && x0 + 1 < 128 && y0 + 1 >= 0 && y0 + 1 < 128)
            v11 = __ldg(&img[(y0 + 1) * 128 + x0 + 1]);
        accum += v00 * (1.f - wx) * (1.f - wy) + v10 * wx * (1.f - wy)
               + v01 * (1.f - wx) * wy + v11 * wx * wy;
    }
    part[sg][tid] = accum;
    __syncthreads();
    if (threadIdx.x < 128)
        out[IMGW * IMGW + a * 128 + threadIdx.x] =
            part[0][threadIdx.x] + part[1][threadIdx.x] +
            part[2][threadIdx.x] + part[3][threadIdx.x];
}

/* ------------------------------- launch ------------------------------------ */
extern "C" void kernel_launch(void* const* d_in, const int* in_sizes, int n_in,
                              void* d_out, int out_size)
{
    const float* sino   = (const float*)d_in[0];
    const float* w1     = (const float*)d_in[1];
    const float* b1     = (const float*)d_in[2];
    const float* w2     = (const float*)d_in[3];
    const float* b2     = (const float*)d_in[4];
    const float* w3     = (const float*)d_in[5];
    const float* b3     = (const float*)d_in[6];
    const float* linw   = (const float*)d_in[7];
    const float* linb   = (const float*)d_in[8];
    const int*   masks  = (const int*)d_in[9];
    float* out = (float*)d_out;

    cudaFuncSetAttribute(conv2s_kernel, cudaFuncAttributeMaxDynamicSharedMemorySize, C2S_SMEM);
    cudaFuncSetAttribute(conv3s_kernel, cudaFuncAttributeMaxDynamicSharedMemorySize, C3S_SMEM);

    prep_kernel<<<73, 256>>>(w2, b1, b2);                       /* 0 */
    anchors_kernel<<<NP, 64>>>(masks);                          /* 1 */
    conv1s_kernel<<<NP, 256>>>(sino, masks, w1, b1);            /* 2 */
    conv2s_kernel<<<dim3(4, NP, 10), 192, C2S_SMEM>>>(b2);      /* 3 <- profiled */
    bg3_kernel<<<60, 128>>>(w3, b3);                            /* 4 */
    xbg_kernel<<<25, 256>>>(linw, linb);                        /* 5 */
    conv3s_kernel<<<dim3(10, NP), 256, C3S_SMEM>>>(w3, b3);     /* 6 */
    gather_kernel<<<NP, 256>>>(linw);                           /* 7 */
    recon_kernel<<<(IMGW * IMGW + 255) / 256, 256>>>(out);      /* 8 */
    radon_kernel<<<NA, 512>>>(out);                             /* 9 */
}